// round 17
// baseline (speedup 1.0000x reference)
#include <cuda_runtime.h>
#include <cuda_bf16.h>

// ---------------------------------------------------------------------------
// GAT-style sparse attention, CSR-fused formulation.  4 launches:
//   csr (hist+scan+degree-sort+edge-scatter, grid barriers)  [s0]
//   bprep [s1]   qkv (mma.sync bf16 hi/lo, at legacy-mma ceiling) [s1]
//   agg (join; degree-sorted node order -> warp-max == mean)  [s0, profiled]
// edge_index arrives as int32.  Plain sm_103 target: mma.sync/ldmatrix/cp.async.
// ---------------------------------------------------------------------------

#define IN_DIM 256
#define HD 32
#define NMAX 100000
#define EMAX 1600000
#define SCAN_BLK 1024

__device__ __align__(16) float g_Q[NMAX * HD];
__device__ __align__(16) float g_KV[NMAX * 64];   // per node: K[0:32) | V[32:64)
__device__ int g_cnt[NMAX];       // zero at load; agg re-zeros for next call
__device__ int g_rowptr[NMAX];
__device__ int g_cursor[NMAX];
__device__ __align__(16) int g_sdst[EMAX];
__device__ int g_order[NMAX];     // degree-sorted node permutation
__device__ int g_bsum[128];
// csr_kernel sync state (all zero at load; self-resetting each run)
__device__ int g_bar1, g_rel1, g_bar2, g_rel2, g_bar3, g_rel3, g_done1;
__device__ int g_ready[128];
__device__ int g_dhist[64];       // degree histogram (zero at load; self-reset)
__device__ int g_dcur[64];        // bucket cursors (re-derived each run)
// Pre-built bf16 hi/lo of B=W^T in padded smem layout:
// [4 chunks][96 rows][36 uints] (144B rows; last 16B padding, never read)
__device__ __align__(16) unsigned g_Bhp[4 * 96 * 36];
__device__ __align__(16) unsigned g_Blp[4 * 96 * 36];

// ---------------------------------------------------------------------------
// helpers
// ---------------------------------------------------------------------------
__device__ __forceinline__ unsigned smem_u32(const void* p)
{
    unsigned a;
    asm("{ .reg .u64 t; cvta.to.shared.u64 t, %1; cvt.u32.u64 %0, t; }"
        : "=r"(a) : "l"(p));
    return a;
}
__device__ __forceinline__ unsigned short bf16h(float x)
{
    return __bfloat16_as_ushort(__float2bfloat16(x));
}
__device__ __forceinline__ float bf16f(unsigned short u)
{
    return __bfloat162float(__ushort_as_bfloat16(u));
}

__device__ __forceinline__ void cp16(unsigned dst, const void* src, int srcsz)
{
    asm volatile("cp.async.cg.shared.global [%0], [%1], 16, %2;"
                 :: "r"(dst),
                    "l"(__cvta_generic_to_global(src)),
                    "r"(srcsz) : "memory");
}
#define CP_COMMIT() asm volatile("cp.async.commit_group;" ::: "memory")
#define CP_WAIT0()  asm volatile("cp.async.wait_group 0;" ::: "memory")

__device__ __forceinline__ void ldsm_x4(unsigned r[4], unsigned addr)
{
    asm volatile("ldmatrix.sync.aligned.m8n8.x4.shared.b16 {%0,%1,%2,%3}, [%4];"
                 : "=r"(r[0]), "=r"(r[1]), "=r"(r[2]), "=r"(r[3]) : "r"(addr));
}
__device__ __forceinline__ void ldsm_x2(unsigned r[2], unsigned addr)
{
    asm volatile("ldmatrix.sync.aligned.m8n8.x2.shared.b16 {%0,%1}, [%2];"
                 : "=r"(r[0]), "=r"(r[1]) : "r"(addr));
}
__device__ __forceinline__ void mma_bf16(float c[4], const unsigned a[4],
                                         const unsigned b[2])
{
    asm volatile("mma.sync.aligned.m16n8k16.row.col.f32.bf16.bf16.f32 "
                 "{%0,%1,%2,%3}, {%4,%5,%6,%7}, {%8,%9}, {%0,%1,%2,%3};"
                 : "+f"(c[0]), "+f"(c[1]), "+f"(c[2]), "+f"(c[3])
                 : "r"(a[0]), "r"(a[1]), "r"(a[2]), "r"(a[3]),
                   "r"(b[0]), "r"(b[1]));
}

// counter grid barrier (one thread spins, block-wide fences via syncthreads)
__device__ __forceinline__ void gridbar(int nb, int* bar, int* rel)
{
    __syncthreads();
    if (threadIdx.x == 0) {
        __threadfence();
        int ticket = atomicAdd(bar, 1);
        if (ticket == nb - 1) atomicExch(rel, 1);
        while (atomicAdd(rel, 0) == 0) {}
        __threadfence();
    }
    __syncthreads();
}

// ---------------------------------------------------------------------------
// B prep: bf16 hi/lo of W^T in PADDED layout (144B rows).  48 blocks.
// ---------------------------------------------------------------------------
__global__ void bprep_kernel(const float* __restrict__ Wq,
                             const float* __restrict__ Wk,
                             const float* __restrict__ Wv)
{
    int idx = blockIdx.x * blockDim.x + threadIdx.x;   // 0..12287
    if (idx >= 12288) return;
    int c   = idx / 3072;
    int rem = idx % 3072;
    int n   = rem / 32;
    int jp  = rem % 32;
    int k0  = c * 64 + 2 * jp;
    const float* Wm = (n < 32) ? Wq : (n < 64) ? Wk : Wv;
    float w0 = Wm[k0 * HD + (n & 31)];
    float w1 = Wm[(k0 + 1) * HD + (n & 31)];
    unsigned short h0 = bf16h(w0), h1 = bf16h(w1);
    unsigned short l0 = bf16h(w0 - bf16f(h0));
    unsigned short l1 = bf16h(w1 - bf16f(h1));
    int g = c * 3456 + n * 36 + jp;
    g_Bhp[g] = (unsigned)h0 | ((unsigned)h1 << 16);
    g_Blp[g] = (unsigned)l0 | ((unsigned)l1 << 16);
}

// ---------------------------------------------------------------------------
// QKV GEMM (byte-identical to R16): mma.sync bf16 hi/lo, BM=128, 8 warps =
// 4 M-pairs x 2 N-halves, LDG X prefetch, cp.async B, 2 CTAs/SM.
// ---------------------------------------------------------------------------
#define ASTRIDE 72
#define SM_AH 0
#define SM_AL 18432
#define SM_BH 36864
#define SM_BL 50688
#define QKV_SMEM 64512

__global__ void __launch_bounds__(256, 2)
qkv_mma_kernel(const float* __restrict__ X, int N)
{
    extern __shared__ char smem[];
    const unsigned sb = smem_u32(smem);
    const int tid   = threadIdx.x;
    const int wid   = tid >> 5;
    const int lane  = tid & 31;
    const int mpair = wid & 3;
    const int nhalf = wid >> 2;
    const int n0    = blockIdx.x * 128;

    float acc[2][6][4];
    #pragma unroll
    for (int s = 0; s < 2; s++)
        #pragma unroll
        for (int j = 0; j < 6; j++)
            #pragma unroll
            for (int i = 0; i < 4; i++) acc[s][j][i] = 0.f;

    const int a_row = (lane & 15);
    const int a_kh  = ((lane >> 4) & 1) * 8;
    const int b_row = (lane & 7);
    const int b_kh  = ((lane >> 3) & 1) * 8;

    float4 xv[8];
    #pragma unroll
    for (int ii = 0; ii < 8; ii++) {
        int q = tid + 256 * ii;
        int r = q >> 4, j4 = q & 15;
        int node = n0 + r;
        xv[ii] = (node < N)
            ? *(const float4*)&X[(size_t)node * IN_DIM + 4 * j4]
            : make_float4(0.f, 0.f, 0.f, 0.f);
    }

    for (int c = 0; c < 4; c++) {
        __syncthreads();

        for (int i = tid; i < 1728; i += 256) {
            if (i < 864)
                cp16(sb + SM_BH + 16 * i,
                     (const char*)g_Bhp + c * 13824 + 16 * i, 16);
            else
                cp16(sb + SM_BL + 16 * (i - 864),
                     (const char*)g_Blp + c * 13824 + 16 * (i - 864), 16);
        }
        CP_COMMIT();

        #pragma unroll
        for (int ii = 0; ii < 8; ii++) {
            int q = tid + 256 * ii;
            int r = q >> 4, j4 = q & 15;
            float4 v = xv[ii];
            unsigned short hx = bf16h(v.x), hy = bf16h(v.y),
                           hz = bf16h(v.z), hw = bf16h(v.w);
            unsigned short lx = bf16h(v.x - bf16f(hx)), ly = bf16h(v.y - bf16f(hy)),
                           lz = bf16h(v.z - bf16f(hz)), lw = bf16h(v.w - bf16f(hw));
            unsigned byte = r * (ASTRIDE * 2) + 8 * j4;
            *(uint2*)(smem + SM_AH + byte) =
                make_uint2((unsigned)hx | ((unsigned)hy << 16),
                           (unsigned)hz | ((unsigned)hw << 16));
            *(uint2*)(smem + SM_AL + byte) =
                make_uint2((unsigned)lx | ((unsigned)ly << 16),
                           (unsigned)lz | ((unsigned)lw << 16));
        }

        if (c < 3) {
            #pragma unroll
            for (int ii = 0; ii < 8; ii++) {
                int q = tid + 256 * ii;
                int r = q >> 4, j4 = q & 15;
                int node = n0 + r;
                xv[ii] = (node < N)
                    ? *(const float4*)&X[(size_t)node * IN_DIM + (c + 1) * 64 + 4 * j4]
                    : make_float4(0.f, 0.f, 0.f, 0.f);
            }
        }

        CP_WAIT0();
        __syncthreads();

        #pragma unroll
        for (int ks = 0; ks < 4; ks++) {
            unsigned ah[2][4], al[2][4];
            #pragma unroll
            for (int s = 0; s < 2; s++) {
                unsigned byte = (mpair * 32 + s * 16 + a_row) * (ASTRIDE * 2)
                              + (ks * 16 + a_kh) * 2;
                ldsm_x4(ah[s], sb + SM_AH + byte);
                ldsm_x4(al[s], sb + SM_AL + byte);
            }
            #pragma unroll
            for (int j = 0; j < 6; j++) {
                int jj = nhalf * 6 + j;
                unsigned bh[2], bl[2];
                unsigned byte = (jj * 8 + b_row) * (ASTRIDE * 2)
                              + (ks * 16 + b_kh) * 2;
                ldsm_x2(bh, sb + SM_BH + byte);
                ldsm_x2(bl, sb + SM_BL + byte);
                #pragma unroll
                for (int s = 0; s < 2; s++) {
                    mma_bf16(acc[s][j], ah[s], bh);
                    mma_bf16(acc[s][j], ah[s], bl);
                    mma_bf16(acc[s][j], al[s], bh);
                }
            }
        }
    }

    const int g  = lane >> 2;
    const int tt = lane & 3;
    #pragma unroll
    for (int s = 0; s < 2; s++) {
        const int row_hi = n0 + mpair * 32 + s * 16 + g;
        const int row_lo = row_hi + 8;
        #pragma unroll
        for (int j = 0; j < 6; j++) {
            int jj  = nhalf * 6 + j;
            int col = 8 * (jj & 3) + 2 * tt;
            float* p_hi;
            float* p_lo;
            if (jj < 4) {
                p_hi = &g_Q[(size_t)row_hi * HD + col];
                p_lo = &g_Q[(size_t)row_lo * HD + col];
            } else if (jj < 8) {
                p_hi = &g_KV[(size_t)row_hi * 64 + col];
                p_lo = &g_KV[(size_t)row_lo * 64 + col];
            } else {
                p_hi = &g_KV[(size_t)row_hi * 64 + 32 + col];
                p_lo = &g_KV[(size_t)row_lo * 64 + 32 + col];
            }
            if (row_hi < N) *(float2*)p_hi = make_float2(acc[s][j][0], acc[s][j][1]);
            if (row_lo < N) *(float2*)p_lo = make_float2(acc[s][j][2], acc[s][j][3]);
        }
    }
}

// ---------------------------------------------------------------------------
// CSR mega-kernel: hist -> scan -> degree counting-sort -> edge scatter.
// nb blocks (<=128, all resident).  All sync state self-resets each run.
// ---------------------------------------------------------------------------
__global__ void __launch_bounds__(SCAN_BLK)
csr_kernel(const int* __restrict__ ei, int E, int N, int nb)
{
    __shared__ int wsum[32];
    __shared__ int sh2[128];
    __shared__ int s_boff;

    const int t    = threadIdx.x;
    const int lane = t & 31;
    const int wid  = t >> 5;
    const int b    = blockIdx.x;
    const int gtid = b * SCAN_BLK + t;
    const int gsz  = nb * SCAN_BLK;

    // ---- P1: histogram over src (int4 grid-stride) ----
    const int nquad = E >> 2;
    for (int q = gtid; q < nquad; q += gsz) {
        int4 s = ((const int4*)ei)[q];
        atomicAdd(&g_cnt[s.x], 1);
        atomicAdd(&g_cnt[s.y], 1);
        atomicAdd(&g_cnt[s.z], 1);
        atomicAdd(&g_cnt[s.w], 1);
    }
    for (int e = (nquad << 2) + gtid; e < E; e += gsz)
        atomicAdd(&g_cnt[ei[e]], 1);

    gridbar(nb, &g_bar1, &g_rel1);

    // ---- P2: exclusive scan of counts; degree histogram ----
    const int i = gtid;
    const int deg = (i < N) ? g_cnt[i] : 0;
    int x = deg;
    #pragma unroll
    for (int off = 1; off < 32; off <<= 1) {
        int y = __shfl_up_sync(0xffffffffu, x, off);
        if (lane >= off) x += y;
    }
    if (lane == 31) wsum[wid] = x;
    __syncthreads();
    if (wid == 0) {
        int s = wsum[lane];
        #pragma unroll
        for (int off = 1; off < 32; off <<= 1) {
            int y = __shfl_up_sync(0xffffffffu, s, off);
            if (lane >= off) s += y;
        }
        wsum[lane] = s;
    }
    __syncthreads();
    const int base = (wid > 0) ? wsum[wid - 1] : 0;
    const int excl = base + x - deg;

    if (t == SCAN_BLK - 1) {
        g_bsum[b] = base + x;
        __threadfence();
        atomicExch(&g_ready[b], 1);
    }

    int val = 0;
    if (t < nb) {
        while (atomicAdd(&g_ready[t], 0) == 0) {}
        __threadfence();
        val = g_bsum[t];
    }
    if (t < 128) sh2[t] = (t < nb) ? val : 0;
    __syncthreads();
    #pragma unroll
    for (int off = 1; off < 128; off <<= 1) {
        int y = (t < 128 && t >= off) ? sh2[t - off] : 0;
        __syncthreads();
        if (t < 128) sh2[t] += y;
        __syncthreads();
    }
    if (t == b) s_boff = sh2[b] - val;
    __syncthreads();

    const int bucket = (deg < 63) ? deg : 63;
    if (i < N) {
        int rp = s_boff + excl;
        g_rowptr[i] = rp;
        g_cursor[i] = rp;
        atomicAdd(&g_dhist[bucket], 1);
    }

    gridbar(nb, &g_bar2, &g_rel2);   // cursor + dhist complete

    // ---- P3: block 0 derives bucket offsets ----
    if (b == 0) {
        int dv = (t < 64) ? g_dhist[t] : 0;
        if (t < 64) sh2[t] = dv;
        __syncthreads();
        #pragma unroll
        for (int off = 1; off < 64; off <<= 1) {
            int y = (t < 64 && t >= off) ? sh2[t - off] : 0;
            __syncthreads();
            if (t < 64) sh2[t] += y;
            __syncthreads();
        }
        if (t < 64) g_dcur[t] = sh2[t] - dv;   // exclusive bucket offsets
    }

    gridbar(nb, &g_bar3, &g_rel3);   // dcur visible

    // ---- P4: node order scatter + edge scatter ----
    if (i < N) {
        int pos = atomicAdd(&g_dcur[bucket], 1);
        g_order[pos] = i;
    }
    for (int q = gtid; q < nquad; q += gsz) {
        int4 s = ((const int4*)ei)[q];
        int4 d = ((const int4*)&ei[E])[q];
        g_sdst[atomicAdd(&g_cursor[s.x], 1)] = d.x;
        g_sdst[atomicAdd(&g_cursor[s.y], 1)] = d.y;
        g_sdst[atomicAdd(&g_cursor[s.z], 1)] = d.z;
        g_sdst[atomicAdd(&g_cursor[s.w], 1)] = d.w;
    }
    for (int e = (nquad << 2) + gtid; e < E; e += gsz) {
        int s = ei[e];
        int d = ei[E + e];
        g_sdst[atomicAdd(&g_cursor[s], 1)] = d;
    }

    // ---- reset sync state (last block out) ----
    __syncthreads();
    if (t == 0) {
        int d = atomicAdd(&g_done1, 1);
        if (d == nb - 1) {
            for (int k = 0; k < nb; k++) g_ready[k] = 0;
            for (int k = 0; k < 64; k++) g_dhist[k] = 0;
            g_bar1 = 0; g_rel1 = 0;
            g_bar2 = 0; g_rel2 = 0;
            g_bar3 = 0; g_rel3 = 0;
            g_done1 = 0;
            __threadfence();
        }
    }
}

// ---------------------------------------------------------------------------
// Fused softmax + aggregate: 4 nodes/warp via degree-sorted g_order
// (equal-degree groups -> warp-max trip == per-node trip).
// One 8-lane group per node, 2-edge unroll with index prefetch.
// ---------------------------------------------------------------------------
__global__ void __launch_bounds__(256)
agg_kernel(float* __restrict__ out, int N)
{
    const int lane = threadIdx.x & 31;
    const int warp = (blockIdx.x * blockDim.x + threadIdx.x) >> 5;
    const int grp  = lane >> 3;
    const int sub  = lane & 7;
    const int idx  = warp * 4 + grp;
    const bool nvalid = (idx < N);
    const int n    = nvalid ? g_order[idx] : 0;

    const float4 q4 = *(const float4*)&g_Q[(size_t)n * HD + sub * 4];
    const int rs  = g_rowptr[n];
    const int cnt = nvalid ? g_cnt[n] : 0;

    int nit = (cnt + 1) >> 1;
    nit = max(nit, __shfl_xor_sync(0xffffffffu, nit, 8));
    nit = max(nit, __shfl_xor_sync(0xffffffffu, nit, 16));

    float4 acc = make_float4(0.f, 0.f, 0.f, 0.f);
    float  sw  = 0.f;

    bool v0 = (0 < cnt);
    bool v1 = (1 < cnt);
    int  d0 = v0 ? g_sdst[rs] : 0;
    int  d1 = v1 ? g_sdst[rs + 1] : 0;

    for (int it = 0; it < nit; it++) {
        float4 k0 = make_float4(0.f, 0.f, 0.f, 0.f), u0 = k0, k1 = k0, u1 = k0;
        if (v0) {
            const float* kv = &g_KV[(size_t)d0 * 64];
            k0 = *(const float4*)&kv[sub * 4];
            u0 = *(const float4*)&kv[32 + sub * 4];
        }
        if (v1) {
            const float* kv = &g_KV[(size_t)d1 * 64];
            k1 = *(const float4*)&kv[sub * 4];
            u1 = *(const float4*)&kv[32 + sub * 4];
        }

        bool nv0 = false, nv1 = false;
        int  nd0 = 0, nd1 = 0;
        {
            int e = (it + 1) * 2;
            nv0 = (e < cnt);
            nv1 = (e + 1 < cnt);
            nd0 = nv0 ? g_sdst[rs + e] : 0;
            nd1 = nv1 ? g_sdst[rs + e + 1] : 0;
        }

        float p0 = q4.x * k0.x + q4.y * k0.y + q4.z * k0.z + q4.w * k0.w;
        float p1 = q4.x * k1.x + q4.y * k1.y + q4.z * k1.z + q4.w * k1.w;
        p0 += __shfl_xor_sync(0xffffffffu, p0, 1);
        p1 += __shfl_xor_sync(0xffffffffu, p1, 1);
        p0 += __shfl_xor_sync(0xffffffffu, p0, 2);
        p1 += __shfl_xor_sync(0xffffffffu, p1, 2);
        p0 += __shfl_xor_sync(0xffffffffu, p0, 4);
        p1 += __shfl_xor_sync(0xffffffffu, p1, 4);

        float w0 = v0 ? __expf(p0 * 0.17677669529663687f) : 0.f;
        float w1 = v1 ? __expf(p1 * 0.17677669529663687f) : 0.f;
        sw += w0 + w1;

        acc.x += w0 * u0.x + w1 * u1.x;
        acc.y += w0 * u0.y + w1 * u1.y;
        acc.z += w0 * u0.z + w1 * u1.z;
        acc.w += w0 * u0.w + w1 * u1.w;

        v0 = nv0; v1 = nv1; d0 = nd0; d1 = nd1;
    }

    if (nvalid) {
        if (sub == 0) g_cnt[n] = 0;   // reset for next call's histogram
        float inv = (sw > 0.f) ? (1.f / sw) : 0.f;
        float4 o = make_float4(acc.x * inv, acc.y * inv, acc.z * inv, acc.w * inv);
        *(float4*)&out[(size_t)n * HD + sub * 4] = o;
    }
}

// ---------------------------------------------------------------------------
// Launch: 4 kernels, fork-join across two streams.
//   csr(1,s0)  bprep(2,s1)  qkv(3,s1)  agg(4,s0 <- profiled)
// ---------------------------------------------------------------------------
extern "C" void kernel_launch(void* const* d_in, const int* in_sizes, int n_in,
                              void* d_out, int out_size)
{
    const float* X  = (const float*)d_in[0];
    const int*   ei = (const int*)d_in[1];     // int32 edge indices
    const float* Wq = (const float*)d_in[2];
    const float* Wk = (const float*)d_in[3];
    const float* Wv = (const float*)d_in[4];
    float* out = (float*)d_out;

    const int N = in_sizes[0] / IN_DIM;
    const int E = in_sizes[1] / 2;
    const int nb = (N + SCAN_BLK - 1) / SCAN_BLK;   // 98 for N=100000 (<=128)

    static cudaStream_t s1 = nullptr;
    static cudaEvent_t  evF = nullptr, evA = nullptr;
    if (!s1) {
        cudaFuncSetAttribute(qkv_mma_kernel,
                             cudaFuncAttributeMaxDynamicSharedMemorySize,
                             QKV_SMEM);
        cudaStreamCreateWithFlags(&s1, cudaStreamNonBlocking);
        cudaEventCreateWithFlags(&evF, cudaEventDisableTiming);
        cudaEventCreateWithFlags(&evA, cudaEventDisableTiming);
    }

    // Fork
    cudaEventRecord(evF, 0);
    cudaStreamWaitEvent(s1, evF, 0);

    csr_kernel<<<nb, SCAN_BLK>>>(ei, E, N, nb);                        // 1
    bprep_kernel<<<48, 256, 0, s1>>>(Wq, Wk, Wv);                      // 2
    qkv_mma_kernel<<<(N + 127) / 128, 256, QKV_SMEM, s1>>>(X, N);      // 3
    cudaEventRecord(evA, s1);

    // Join
    cudaStreamWaitEvent(0, evA, 0);
    agg_kernel<<<((N * 8) + 255) / 256, 256>>>(out, N);                // 4 <- profiled
}